// round 1
// baseline (speedup 1.0000x reference)
#include <cuda_runtime.h>
#include <cuda_bf16.h>
#include <math.h>

#define BATCH  64
#define NPTS   128
#define FEAT   4
#define HID    100
#define NPAIRS 8128   // C(128,2)

// Precomputed folded weights:
//   g_M[f][k] = sum_t W1[f][t] * W2[t][k]   (f in 0..7)
//   g_d[k]    = b2[k] + sum_t b1[t] * W2[t][k]
__device__ float g_M[8 * HID];
__device__ float g_d[HID];

// Upper-triangular 4x4 tile list (32x32 tiles over the 128x128 (i,j) space)
__constant__ int TCI[10] = {0,0,0,0,1,1,1,2,2,3};
__constant__ int TCJ[10] = {0,1,2,3,1,2,3,2,3,3};

// ---------------------------------------------------------------------------
// Kernel 1: fold W1@W2 and b1@W2+b2 into g_M / g_d  (tiny)
// ---------------------------------------------------------------------------
__global__ void prep_kernel(const float* __restrict__ W1,   // [8,100]
                            const float* __restrict__ b1,   // [100]
                            const float* __restrict__ W2,   // [100,100]
                            const float* __restrict__ b2)   // [100]
{
    int k = threadIdx.x;
    if (k >= HID) return;
    float m0 = 0.f, m1 = 0.f, m2 = 0.f, m3 = 0.f;
    float m4 = 0.f, m5 = 0.f, m6 = 0.f, m7 = 0.f;
    float dv = 0.f;
    for (int t = 0; t < HID; t++) {
        float w2 = W2[t * HID + k];          // coalesced across k
        m0 = fmaf(W1[0 * HID + t], w2, m0);
        m1 = fmaf(W1[1 * HID + t], w2, m1);
        m2 = fmaf(W1[2 * HID + t], w2, m2);
        m3 = fmaf(W1[3 * HID + t], w2, m3);
        m4 = fmaf(W1[4 * HID + t], w2, m4);
        m5 = fmaf(W1[5 * HID + t], w2, m5);
        m6 = fmaf(W1[6 * HID + t], w2, m6);
        m7 = fmaf(W1[7 * HID + t], w2, m7);
        dv = fmaf(b1[t], w2, dv);
    }
    g_M[0 * HID + k] = m0;  g_M[1 * HID + k] = m1;
    g_M[2 * HID + k] = m2;  g_M[3 * HID + k] = m3;
    g_M[4 * HID + k] = m4;  g_M[5 * HID + k] = m5;
    g_M[6 * HID + k] = m6;  g_M[7 * HID + k] = m7;
    g_d[k] = dv + b2[k];
}

// ---------------------------------------------------------------------------
// Kernel 2: per-pair  out = sigmoid( b3 + sum_k relu(a[i][k]+c[j][k]) * W3[k] )
// Grid: 64 batches x 10 tiles (32x32 (i,j) tiles, cj >= ci). 128 threads.
// Thread register tile: 4 i's x 2 j's.  Smem k-major for conflict-free LDS.
// ---------------------------------------------------------------------------
__global__ __launch_bounds__(128)
void pair_kernel(const float* __restrict__ x,    // [64,128,4]
                 const float* __restrict__ W3,   // [100]
                 const float* __restrict__ b3,   // [1]
                 float* __restrict__ out)        // [64, 8128]
{
    __shared__ __align__(16) float aT[HID * 32];   // aT[k*32 + ii], d folded in
    __shared__ __align__(16) float cT[HID * 32];   // cT[k*32 + jj]
    __shared__ float ws[HID];
    __shared__ float xi[32 * 5];                   // padded stride 5: no bank conflicts
    __shared__ float xj[32 * 5];

    const int tid  = threadIdx.x;
    const int tile = blockIdx.x % 10;
    const int b    = blockIdx.x / 10;
    const int i0   = TCI[tile] * 32;
    const int j0   = TCJ[tile] * 32;

    const int tj = tid & 15;     // 16 j-groups (fast -> coalesced stores)
    const int ti = tid >> 4;     // 8 i-groups

    // --- stage x tiles (128 floats each; 1 float/thread) ---
    {
        int r = tid >> 2, f = tid & 3;
        xi[r * 5 + f] = x[((size_t)b * NPTS + (i0 + r)) * FEAT + f];
        xj[r * 5 + f] = x[((size_t)b * NPTS + (j0 + r)) * FEAT + f];
        if (tid < HID) ws[tid] = W3[tid];
    }
    __syncthreads();

    // --- compute aT / cT : 3200 elements each, 25 per thread ---
    for (int e = tid; e < 32 * HID; e += 128) {
        int k  = e >> 5;
        int ii = e & 31;
        float ma0 = g_M[0 * HID + k], ma1 = g_M[1 * HID + k];
        float ma2 = g_M[2 * HID + k], ma3 = g_M[3 * HID + k];
        float mc0 = g_M[4 * HID + k], mc1 = g_M[5 * HID + k];
        float mc2 = g_M[6 * HID + k], mc3 = g_M[7 * HID + k];
        float av = g_d[k];
        av = fmaf(xi[ii * 5 + 0], ma0, av);
        av = fmaf(xi[ii * 5 + 1], ma1, av);
        av = fmaf(xi[ii * 5 + 2], ma2, av);
        av = fmaf(xi[ii * 5 + 3], ma3, av);
        float cv;
        cv =            xj[ii * 5 + 0] * mc0;
        cv = fmaf(xj[ii * 5 + 1], mc1, cv);
        cv = fmaf(xj[ii * 5 + 2], mc2, cv);
        cv = fmaf(xj[ii * 5 + 3], mc3, cv);
        aT[k * 32 + ii] = av;
        cT[k * 32 + ii] = cv;
    }
    __syncthreads();

    // --- main loop: 8 pair-slots per thread, k-contraction ---
    float acc[8] = {0.f, 0.f, 0.f, 0.f, 0.f, 0.f, 0.f, 0.f};
    const float* aP = aT + ti * 4;     // 16B aligned
    const float* cP = cT + tj * 2;     //  8B aligned

    #pragma unroll 4
    for (int k = 0; k < HID; k++) {
        float4 av = *reinterpret_cast<const float4*>(aP + k * 32);  // LDS.128 (broadcast-heavy)
        float2 cv = *reinterpret_cast<const float2*>(cP + k * 32);  // LDS.64  (coalesced)
        float  w  = ws[k];                                          // broadcast
        float a0 = av.x, a1 = av.y, a2 = av.z, a3 = av.w;
        acc[0] = fmaf(fmaxf(a0 + cv.x, 0.f), w, acc[0]);
        acc[1] = fmaf(fmaxf(a0 + cv.y, 0.f), w, acc[1]);
        acc[2] = fmaf(fmaxf(a1 + cv.x, 0.f), w, acc[2]);
        acc[3] = fmaf(fmaxf(a1 + cv.y, 0.f), w, acc[3]);
        acc[4] = fmaf(fmaxf(a2 + cv.x, 0.f), w, acc[4]);
        acc[5] = fmaf(fmaxf(a2 + cv.y, 0.f), w, acc[5]);
        acc[6] = fmaf(fmaxf(a3 + cv.x, 0.f), w, acc[6]);
        acc[7] = fmaf(fmaxf(a3 + cv.y, 0.f), w, acc[7]);
    }

    // --- epilogue: sigmoid + masked triangular store ---
    const float bias3 = b3[0];
    float* outb = out + (size_t)b * NPAIRS;
    #pragma unroll
    for (int pi = 0; pi < 4; pi++) {
        int i  = i0 + ti * 4 + pi;
        // p = i*(N-1) - i*(i-1)/2 + (j - i - 1)
        int rb = i * (NPTS - 1) - ((i * (i - 1)) >> 1) - i - 1;
        #pragma unroll
        for (int pj = 0; pj < 2; pj++) {
            int j = j0 + tj * 2 + pj;
            if (j > i) {
                float v = bias3 + acc[pi * 2 + pj];
                outb[rb + j] = 1.f / (1.f + __expf(-v));
            }
        }
    }
}

// ---------------------------------------------------------------------------
extern "C" void kernel_launch(void* const* d_in, const int* in_sizes, int n_in,
                              void* d_out, int out_size)
{
    const float* x   = (const float*)d_in[0];
    // d_in[1] = in_hitnr (unused by the reference)
    const float* W1  = (const float*)d_in[2];
    const float* b1  = (const float*)d_in[3];
    const float* W2  = (const float*)d_in[4];
    const float* b2  = (const float*)d_in[5];
    const float* W3  = (const float*)d_in[6];
    const float* b3  = (const float*)d_in[7];
    float* out = (float*)d_out;

    prep_kernel<<<1, 128>>>(W1, b1, W2, b2);
    pair_kernel<<<BATCH * 10, 128>>>(x, W3, b3, out);
}

// round 2
// speedup vs baseline: 1.4100x; 1.4100x over previous
#include <cuda_runtime.h>
#include <cuda_bf16.h>
#include <math.h>

#define BATCH  64
#define NPTS   128
#define FEAT   4
#define HID    100
#define NPAIRS 8128   // C(128,2)

// Folded weights: g_M[f][k] = sum_t W1[f][t]*W2[t][k]  (f 0..7)
//                 g_d[k]    = b2[k] + sum_t b1[t]*W2[t][k]
__device__ float g_M[8 * HID];
__device__ float g_d[HID];

// Precomputed per-point projections, k-major:
//   g_A[b][k][i] = g_d[k] + sum_f x[b][i][f] * g_M[f][k]       (i-part, bias folded)
//   g_C[b][k][j] =          sum_f x[b][j][f] * g_M[4+f][k]     (j-part)
__device__ __align__(16) float g_A[BATCH * HID * NPTS];   // 3.125 MB
__device__ __align__(16) float g_C[BATCH * HID * NPTS];

// 16x16 tile list over the 8x8 upper triangle (jt >= it): 36 tiles
__constant__ unsigned char TCI[36] = {0,0,0,0,0,0,0,0, 1,1,1,1,1,1,1, 2,2,2,2,2,2,
                                      3,3,3,3,3, 4,4,4,4, 5,5,5, 6,6, 7};
__constant__ unsigned char TCJ[36] = {0,1,2,3,4,5,6,7, 1,2,3,4,5,6,7, 2,3,4,5,6,7,
                                      3,4,5,6,7, 4,5,6,7, 5,6,7, 6,7, 7};

// ---------------------------------------------------------------------------
// Kernel 1: fold W1@W2, b1@W2+b2.  One warp per k (100 warps = 25 CTAs).
// ---------------------------------------------------------------------------
__global__ __launch_bounds__(128)
void fold_kernel(const float* __restrict__ W1,   // [8,100]
                 const float* __restrict__ b1,   // [100]
                 const float* __restrict__ W2,   // [100,100]
                 const float* __restrict__ b2)   // [100]
{
    const int warp = threadIdx.x >> 5;
    const int lid  = threadIdx.x & 31;
    const int k    = blockIdx.x * 4 + warp;      // 0..99

    float acc[9] = {0.f,0.f,0.f,0.f,0.f,0.f,0.f,0.f,0.f};
    for (int t = lid; t < HID; t += 32) {
        float w2 = W2[t * HID + k];
        #pragma unroll
        for (int f = 0; f < 8; f++)
            acc[f] = fmaf(W1[f * HID + t], w2, acc[f]);
        acc[8] = fmaf(b1[t], w2, acc[8]);
    }
    #pragma unroll
    for (int off = 16; off > 0; off >>= 1) {
        #pragma unroll
        for (int q = 0; q < 9; q++)
            acc[q] += __shfl_down_sync(0xffffffffu, acc[q], off);
    }
    if (lid == 0) {
        #pragma unroll
        for (int f = 0; f < 8; f++)
            g_M[f * HID + k] = acc[f];
        g_d[k] = acc[8] + b2[k];
    }
}

// ---------------------------------------------------------------------------
// Kernel 2: materialize A and C (k-major).  Grid (64 batches, 2 k-halves).
// ---------------------------------------------------------------------------
__global__ __launch_bounds__(256)
void precomp_kernel(const float* __restrict__ x)   // [64,128,4]
{
    __shared__ float4 xs[NPTS];
    __shared__ float  Ms[8 * HID];
    __shared__ float  ds[HID];

    const int tid = threadIdx.x;
    const int b   = blockIdx.x;
    const int h   = blockIdx.y;          // k half: [h*50, h*50+50)

    if (tid < NPTS) xs[tid] = reinterpret_cast<const float4*>(x)[b * NPTS + tid];
    for (int e = tid; e < 8 * HID; e += 256) Ms[e] = g_M[e];
    if (tid < HID) ds[tid] = g_d[tid];
    __syncthreads();

    float* Ab = g_A + (size_t)b * (HID * NPTS);
    float* Cb = g_C + (size_t)b * (HID * NPTS);

    for (int e = tid; e < 50 * NPTS; e += 256) {
        int i  = e & (NPTS - 1);
        int k  = h * 50 + (e >> 7);
        float4 xv = xs[i];
        float a = ds[k];
        a = fmaf(xv.x, Ms[0 * HID + k], a);
        a = fmaf(xv.y, Ms[1 * HID + k], a);
        a = fmaf(xv.z, Ms[2 * HID + k], a);
        a = fmaf(xv.w, Ms[3 * HID + k], a);
        float c;
        c =      xv.x * Ms[4 * HID + k];
        c = fmaf(xv.y, Ms[5 * HID + k], c);
        c = fmaf(xv.z, Ms[6 * HID + k], c);
        c = fmaf(xv.w, Ms[7 * HID + k], c);
        Ab[k * NPTS + i] = a;    // coalesced (i fast)
        Cb[k * NPTS + i] = c;
    }
}

// ---------------------------------------------------------------------------
// Kernel 3: pair tiles.  16x16 (i,j) tiles, 64 threads, 2i x 2j per thread.
// Grid (36 tiles, 64 batches) = 2304 CTAs.
// ---------------------------------------------------------------------------
__global__ __launch_bounds__(64)
void pair_kernel(const float* __restrict__ W3,   // [100]
                 const float* __restrict__ b3,   // [1]
                 float* __restrict__ out)        // [64, 8128]
{
    __shared__ __align__(16) float aS[HID * 16];   // aS[k*16 + ii]
    __shared__ __align__(16) float cS[HID * 16];
    __shared__ float ws[HID];

    const int tid  = threadIdx.x;
    const int tile = blockIdx.x;
    const int b    = blockIdx.y;
    const int i0   = TCI[tile] * 16;
    const int j0   = TCJ[tile] * 16;

    const int tj = tid & 7;       // 8 j-groups of 2
    const int ti = tid >> 3;      // 8 i-groups of 2

    // --- prologue: pull A/C rows from L2 (float4, coalesced per k-row) ---
    const float* Ab = g_A + (size_t)b * (HID * NPTS) + i0;
    const float* Cb = g_C + (size_t)b * (HID * NPTS) + j0;
    for (int q = tid; q < 4 * HID; q += 64) {       // 400 float4s
        int k   = q >> 2;
        int ii4 = (q & 3) << 2;
        *reinterpret_cast<float4*>(aS + k * 16 + ii4) =
            *reinterpret_cast<const float4*>(Ab + k * NPTS + ii4);
        *reinterpret_cast<float4*>(cS + k * 16 + ii4) =
            *reinterpret_cast<const float4*>(Cb + k * NPTS + ii4);
    }
    for (int q = tid; q < HID; q += 64) ws[q] = W3[q];
    __syncthreads();

    // --- main loop: 2x2 slots, k contraction ---
    float acc0 = 0.f, acc1 = 0.f, acc2 = 0.f, acc3 = 0.f;
    const float* aP = aS + ti * 2;
    const float* cP = cS + tj * 2;

    #pragma unroll 4
    for (int k = 0; k < HID; k++) {
        float2 a2 = *reinterpret_cast<const float2*>(aP + k * 16);
        float2 c2 = *reinterpret_cast<const float2*>(cP + k * 16);
        float  w  = ws[k];
        acc0 = fmaf(fmaxf(a2.x + c2.x, 0.f), w, acc0);
        acc1 = fmaf(fmaxf(a2.x + c2.y, 0.f), w, acc1);
        acc2 = fmaf(fmaxf(a2.y + c2.x, 0.f), w, acc2);
        acc3 = fmaf(fmaxf(a2.y + c2.y, 0.f), w, acc3);
    }

    // --- epilogue: sigmoid + masked upper-triangular store ---
    const float bias3 = b3[0];
    float* outb = out + (size_t)b * NPAIRS;
    float accv[4] = {acc0, acc1, acc2, acc3};
    #pragma unroll
    for (int pi = 0; pi < 2; pi++) {
        int i  = i0 + ti * 2 + pi;
        int rb = i * (NPTS - 1) - ((i * (i - 1)) >> 1) - i - 1;
        #pragma unroll
        for (int pj = 0; pj < 2; pj++) {
            int j = j0 + tj * 2 + pj;
            if (j > i) {
                float v = bias3 + accv[pi * 2 + pj];
                outb[rb + j] = 1.f / (1.f + __expf(-v));
            }
        }
    }
}

// ---------------------------------------------------------------------------
extern "C" void kernel_launch(void* const* d_in, const int* in_sizes, int n_in,
                              void* d_out, int out_size)
{
    const float* x   = (const float*)d_in[0];
    // d_in[1] = in_hitnr (unused by the reference)
    const float* W1  = (const float*)d_in[2];
    const float* b1  = (const float*)d_in[3];
    const float* W2  = (const float*)d_in[4];
    const float* b2  = (const float*)d_in[5];
    const float* W3  = (const float*)d_in[6];
    const float* b3  = (const float*)d_in[7];
    float* out = (float*)d_out;

    fold_kernel<<<25, 128>>>(W1, b1, W2, b2);
    precomp_kernel<<<dim3(BATCH, 2), 256>>>(x);
    pair_kernel<<<dim3(36, BATCH), 64>>>(W3, b3, out);
}